// round 6
// baseline (speedup 1.0000x reference)
#include <cuda_runtime.h>
#include <cstddef>

#define NN   2048
#define DIN  256

// Scratch (device globals — no allocation allowed in kernel_launch)
__device__ float g_proj[NN * DIN];            // 2 MB: [Q | K | V | R] per row
__device__ float g_S[(size_t)NN * NN];        // 16 MB: scale * Q @ K^T

// ---------------------------------------------------------------------------
// Generic C = alpha * A(MxK, lda) @ B^T(NxK, ldb), 64x64 tiles, K multiple of 64
// grid: (Ntiles, Mtiles), block: 256 threads, each thread computes 4x4
// ---------------------------------------------------------------------------
__global__ __launch_bounds__(256) void gemm_nt(
    const float* __restrict__ A, int lda,
    const float* __restrict__ B, int ldb,
    float* __restrict__ C, int ldc,
    int K, float alpha)
{
    __shared__ float As[64][65];
    __shared__ float Bs[64][65];
    const int tid = threadIdx.x;
    const int tx = tid & 15, ty = tid >> 4;
    const int rb = blockIdx.y * 64, cb = blockIdx.x * 64;

    float acc[4][4] = {};

    for (int kt = 0; kt < K; kt += 64) {
        #pragma unroll
        for (int it = 0; it < 4; it++) {
            int f  = tid + it * 256;          // 0..1023
            int r  = f >> 4;
            int c4 = (f & 15) << 2;
            float4 a = *(const float4*)(A + (size_t)(rb + r) * lda + kt + c4);
            As[r][c4 + 0] = a.x; As[r][c4 + 1] = a.y;
            As[r][c4 + 2] = a.z; As[r][c4 + 3] = a.w;
            float4 b = *(const float4*)(B + (size_t)(cb + r) * ldb + kt + c4);
            Bs[r][c4 + 0] = b.x; Bs[r][c4 + 1] = b.y;
            Bs[r][c4 + 2] = b.z; Bs[r][c4 + 3] = b.w;
        }
        __syncthreads();
        #pragma unroll 16
        for (int k = 0; k < 64; k++) {
            float ai[4], bj[4];
            #pragma unroll
            for (int i = 0; i < 4; i++) ai[i] = As[ty * 4 + i][k];
            #pragma unroll
            for (int j = 0; j < 4; j++) bj[j] = Bs[tx * 4 + j][k];
            #pragma unroll
            for (int i = 0; i < 4; i++)
                #pragma unroll
                for (int j = 0; j < 4; j++)
                    acc[i][j] = fmaf(ai[i], bj[j], acc[i][j]);
        }
        __syncthreads();
    }

    #pragma unroll
    for (int i = 0; i < 4; i++)
        #pragma unroll
        for (int j = 0; j < 4; j++)
            C[(size_t)(rb + ty * 4 + i) * ldc + cb + tx * 4 + j] = alpha * acc[i][j];
}

// ---------------------------------------------------------------------------
// Main fused kernel: per block, G=4 query rows.
//  Phase 1: w[j][g] = S[i_g][j] + scale * dot(R[i_g], D[i_g, j, :])
//  Phase 2: per-row softmax over j (in shared)
//  Phase 3: out[i_g] = softmax @ V
// ---------------------------------------------------------------------------
__global__ __launch_bounds__(256) void attn_main(
    const float* __restrict__ Dm,     // (N, N, 64)
    const float* __restrict__ proj,   // (N, 256)
    const float* __restrict__ S,      // (N, N), already scaled
    float* __restrict__ out)          // (N, 64)
{
    __shared__ __align__(16) float wsh[NN * 4];   // [j][g], 32 KB
    __shared__ float rbuf[9];
    __shared__ float inv[4];

    const int tid  = threadIdx.x;
    const int lane = tid & 31;
    const int w    = tid >> 5;
    const int i0   = blockIdx.x << 2;
    const float scale = 0.08838834764831845f;     // 1/sqrt(DK+DR)

    // ---------------- Phase 1: weights ----------------
    {
        const int g     = w & 3;                 // this warp's query row
        const int jbase = (w >> 2) * (NN / 2);   // which half of j
        const int sub   = lane >> 4;             // 2 j's per warp
        const int kq    = (lane & 15) << 2;      // 4 elems per lane
        const int irow  = i0 + g;

        const float4 r4 = *(const float4*)(proj + irow * DIN + 192 + kq);
        const float* Srow = S + (size_t)irow * NN;
        const float4* dp  = (const float4*)(Dm + ((size_t)irow * NN + jbase + sub) * 64 + kq);

        #pragma unroll 8
        for (int t = 0; t < NN / 4; t++) {       // 512 iters, 2 j's each
            float4 d4 = *dp;
            dp += 32;                            // advance 2 j rows
            float p = r4.x * d4.x + r4.y * d4.y;
            p = fmaf(r4.z, d4.z, p);
            p = fmaf(r4.w, d4.w, p);
            p += __shfl_xor_sync(0xffffffffu, p, 8);
            p += __shfl_xor_sync(0xffffffffu, p, 4);
            p += __shfl_xor_sync(0xffffffffu, p, 2);
            p += __shfl_xor_sync(0xffffffffu, p, 1);
            if ((lane & 15) == 0) {
                int j = jbase + 2 * t + sub;
                wsh[(j << 2) + g] = fmaf(p, scale, Srow[j]);
            }
        }
    }
    __syncthreads();

    // ---------------- Phase 2: softmax per g ----------------
    #pragma unroll 1
    for (int gg = 0; gg < 4; gg++) {
        float m = -1e30f;
        for (int j = tid; j < NN; j += 256) m = fmaxf(m, wsh[(j << 2) + gg]);
        #pragma unroll
        for (int o = 16; o; o >>= 1) m = fmaxf(m, __shfl_xor_sync(0xffffffffu, m, o));
        if (lane == 0) rbuf[w] = m;
        __syncthreads();
        if (tid == 0) {
            float mm = rbuf[0];
            #pragma unroll
            for (int q = 1; q < 8; q++) mm = fmaxf(mm, rbuf[q]);
            rbuf[8] = mm;
        }
        __syncthreads();
        m = rbuf[8];

        float s = 0.f;
        for (int j = tid; j < NN; j += 256) {
            float e = __expf(wsh[(j << 2) + gg] - m);
            wsh[(j << 2) + gg] = e;
            s += e;
        }
        #pragma unroll
        for (int o = 16; o; o >>= 1) s += __shfl_xor_sync(0xffffffffu, s, o);
        __syncthreads();
        if (lane == 0) rbuf[w] = s;
        __syncthreads();
        if (tid == 0) {
            float ss = 0.f;
            #pragma unroll
            for (int q = 0; q < 8; q++) ss += rbuf[q];
            inv[gg] = 1.0f / ss;
        }
        __syncthreads();
    }

    // ---------------- Phase 3: attn @ V ----------------
    const int d = tid & 63;
    const int h = tid >> 6;     // 4 j-interleaved groups
    float a0 = 0.f, a1 = 0.f, a2 = 0.f, a3 = 0.f;
    const float* Vp = proj + 128 + d;
    #pragma unroll 4
    for (int j = h; j < NN; j += 4) {
        float  v = Vp[(size_t)j * DIN];
        float4 e = *(const float4*)(wsh + (j << 2));
        a0 = fmaf(e.x, v, a0);
        a1 = fmaf(e.y, v, a1);
        a2 = fmaf(e.z, v, a2);
        a3 = fmaf(e.w, v, a3);
    }
    __syncthreads();
    // partial reduce across the 4 h-groups (reuse wsh)
    wsh[(h * 4 + 0) * 64 + d] = a0;
    wsh[(h * 4 + 1) * 64 + d] = a1;
    wsh[(h * 4 + 2) * 64 + d] = a2;
    wsh[(h * 4 + 3) * 64 + d] = a3;
    __syncthreads();
    {
        const int g = h;   // reuse thread mapping: thread (g, d)
        float r = wsh[(0 * 4 + g) * 64 + d] + wsh[(1 * 4 + g) * 64 + d]
                + wsh[(2 * 4 + g) * 64 + d] + wsh[(3 * 4 + g) * 64 + d];
        out[(size_t)(i0 + g) * 64 + d] = r * inv[g];
    }
}

// ---------------------------------------------------------------------------
extern "C" void kernel_launch(void* const* d_in, const int* in_sizes, int n_in,
                              void* d_out, int out_size)
{
    (void)out_size;
    const float *H = nullptr, *Dm = nullptr, *Wp = nullptr;
    for (int i = 0; i < n_in; i++) {
        if      (in_sizes[i] == NN * DIN)  H  = (const float*)d_in[i];
        else if (in_sizes[i] == DIN * DIN) Wp = (const float*)d_in[i];
        else                               Dm = (const float*)d_in[i];
    }

    float* proj = nullptr;
    float* Sp   = nullptr;
    cudaGetSymbolAddress((void**)&proj, g_proj);
    cudaGetSymbolAddress((void**)&Sp,   g_S);

    const float scale = 0.08838834764831845f;   // 1/sqrt(128)

    // 1) proj = H @ W^T   (2048 x 256)
    gemm_nt<<<dim3(DIN / 64, NN / 64), 256>>>(H, DIN, Wp, DIN, proj, DIN, DIN, 1.0f);
    // 2) S = scale * Q @ K^T   (2048 x 2048)
    gemm_nt<<<dim3(NN / 64, NN / 64), 256>>>(proj, DIN, proj + 64, DIN, Sp, NN, 64, scale);
    // 3) fused RD + softmax + @V
    attn_main<<<NN / 4, 256>>>(Dm, proj, Sp, (float*)d_out);
}

// round 7
// speedup vs baseline: 1.0009x; 1.0009x over previous
#include <cuda_runtime.h>
#include <cstddef>

#define NN   2048
#define DIN  256

// Scratch (device globals — no allocation allowed in kernel_launch)
__device__ float g_proj[NN * DIN];            // 2 MB: [Q | K | V | R] per row
__device__ float g_S[(size_t)NN * NN];        // 16 MB: scale * Q @ K^T

// ---------------------------------------------------------------------------
// Generic C = alpha * A(MxK, lda) @ B^T(NxK, ldb), 64x64 tiles, K multiple of 64
// grid: (Ntiles, Mtiles), block: 256 threads, each thread computes 4x4
// ---------------------------------------------------------------------------
__global__ __launch_bounds__(256) void gemm_nt(
    const float* __restrict__ A, int lda,
    const float* __restrict__ B, int ldb,
    float* __restrict__ C, int ldc,
    int K, float alpha)
{
    __shared__ float As[64][65];
    __shared__ float Bs[64][65];
    const int tid = threadIdx.x;
    const int tx = tid & 15, ty = tid >> 4;
    const int rb = blockIdx.y * 64, cb = blockIdx.x * 64;

    float acc[4][4] = {};

    for (int kt = 0; kt < K; kt += 64) {
        #pragma unroll
        for (int it = 0; it < 4; it++) {
            int f  = tid + it * 256;          // 0..1023
            int r  = f >> 4;
            int c4 = (f & 15) << 2;
            float4 a = *(const float4*)(A + (size_t)(rb + r) * lda + kt + c4);
            As[r][c4 + 0] = a.x; As[r][c4 + 1] = a.y;
            As[r][c4 + 2] = a.z; As[r][c4 + 3] = a.w;
            float4 b = *(const float4*)(B + (size_t)(cb + r) * ldb + kt + c4);
            Bs[r][c4 + 0] = b.x; Bs[r][c4 + 1] = b.y;
            Bs[r][c4 + 2] = b.z; Bs[r][c4 + 3] = b.w;
        }
        __syncthreads();
        #pragma unroll 16
        for (int k = 0; k < 64; k++) {
            float ai[4], bj[4];
            #pragma unroll
            for (int i = 0; i < 4; i++) ai[i] = As[ty * 4 + i][k];
            #pragma unroll
            for (int j = 0; j < 4; j++) bj[j] = Bs[tx * 4 + j][k];
            #pragma unroll
            for (int i = 0; i < 4; i++)
                #pragma unroll
                for (int j = 0; j < 4; j++)
                    acc[i][j] = fmaf(ai[i], bj[j], acc[i][j]);
        }
        __syncthreads();
    }

    #pragma unroll
    for (int i = 0; i < 4; i++)
        #pragma unroll
        for (int j = 0; j < 4; j++)
            C[(size_t)(rb + ty * 4 + i) * ldc + cb + tx * 4 + j] = alpha * acc[i][j];
}

// ---------------------------------------------------------------------------
// Main fused kernel: per block, G=4 query rows.
//  Phase 1: w[j][g] = S[i_g][j] + scale * dot(R[i_g], D[i_g, j, :])
//  Phase 2: per-row softmax over j (in shared)
//  Phase 3: out[i_g] = softmax @ V
// ---------------------------------------------------------------------------
__global__ __launch_bounds__(256) void attn_main(
    const float* __restrict__ Dm,     // (N, N, 64)
    const float* __restrict__ proj,   // (N, 256)
    const float* __restrict__ S,      // (N, N), already scaled
    float* __restrict__ out)          // (N, 64)
{
    __shared__ __align__(16) float wsh[NN * 4];   // [j][g], 32 KB
    __shared__ float rbuf[9];
    __shared__ float inv[4];

    const int tid  = threadIdx.x;
    const int lane = tid & 31;
    const int w    = tid >> 5;
    const int i0   = blockIdx.x << 2;
    const float scale = 0.08838834764831845f;     // 1/sqrt(DK+DR)

    // ---------------- Phase 1: weights ----------------
    {
        const int g     = w & 3;                 // this warp's query row
        const int jbase = (w >> 2) * (NN / 2);   // which half of j
        const int sub   = lane >> 4;             // 2 j's per warp
        const int kq    = (lane & 15) << 2;      // 4 elems per lane
        const int irow  = i0 + g;

        const float4 r4 = *(const float4*)(proj + irow * DIN + 192 + kq);
        const float* Srow = S + (size_t)irow * NN;
        const float4* dp  = (const float4*)(Dm + ((size_t)irow * NN + jbase + sub) * 64 + kq);

        #pragma unroll 8
        for (int t = 0; t < NN / 4; t++) {       // 512 iters, 2 j's each
            float4 d4 = *dp;
            dp += 32;                            // advance 2 j rows
            float p = r4.x * d4.x + r4.y * d4.y;
            p = fmaf(r4.z, d4.z, p);
            p = fmaf(r4.w, d4.w, p);
            p += __shfl_xor_sync(0xffffffffu, p, 8);
            p += __shfl_xor_sync(0xffffffffu, p, 4);
            p += __shfl_xor_sync(0xffffffffu, p, 2);
            p += __shfl_xor_sync(0xffffffffu, p, 1);
            if ((lane & 15) == 0) {
                int j = jbase + 2 * t + sub;
                wsh[(j << 2) + g] = fmaf(p, scale, Srow[j]);
            }
        }
    }
    __syncthreads();

    // ---------------- Phase 2: softmax per g ----------------
    #pragma unroll 1
    for (int gg = 0; gg < 4; gg++) {
        float m = -1e30f;
        for (int j = tid; j < NN; j += 256) m = fmaxf(m, wsh[(j << 2) + gg]);
        #pragma unroll
        for (int o = 16; o; o >>= 1) m = fmaxf(m, __shfl_xor_sync(0xffffffffu, m, o));
        if (lane == 0) rbuf[w] = m;
        __syncthreads();
        if (tid == 0) {
            float mm = rbuf[0];
            #pragma unroll
            for (int q = 1; q < 8; q++) mm = fmaxf(mm, rbuf[q]);
            rbuf[8] = mm;
        }
        __syncthreads();
        m = rbuf[8];

        float s = 0.f;
        for (int j = tid; j < NN; j += 256) {
            float e = __expf(wsh[(j << 2) + gg] - m);
            wsh[(j << 2) + gg] = e;
            s += e;
        }
        #pragma unroll
        for (int o = 16; o; o >>= 1) s += __shfl_xor_sync(0xffffffffu, s, o);
        __syncthreads();
        if (lane == 0) rbuf[w] = s;
        __syncthreads();
        if (tid == 0) {
            float ss = 0.f;
            #pragma unroll
            for (int q = 0; q < 8; q++) ss += rbuf[q];
            inv[gg] = 1.0f / ss;
        }
        __syncthreads();
    }

    // ---------------- Phase 3: attn @ V ----------------
    const int d = tid & 63;
    const int h = tid >> 6;     // 4 j-interleaved groups
    float a0 = 0.f, a1 = 0.f, a2 = 0.f, a3 = 0.f;
    const float* Vp = proj + 128 + d;
    #pragma unroll 4
    for (int j = h; j < NN; j += 4) {
        float  v = Vp[(size_t)j * DIN];
        float4 e = *(const float4*)(wsh + (j << 2));
        a0 = fmaf(e.x, v, a0);
        a1 = fmaf(e.y, v, a1);
        a2 = fmaf(e.z, v, a2);
        a3 = fmaf(e.w, v, a3);
    }
    __syncthreads();
    // partial reduce across the 4 h-groups (reuse wsh)
    wsh[(h * 4 + 0) * 64 + d] = a0;
    wsh[(h * 4 + 1) * 64 + d] = a1;
    wsh[(h * 4 + 2) * 64 + d] = a2;
    wsh[(h * 4 + 3) * 64 + d] = a3;
    __syncthreads();
    {
        const int g = h;   // reuse thread mapping: thread (g, d)
        float r = wsh[(0 * 4 + g) * 64 + d] + wsh[(1 * 4 + g) * 64 + d]
                + wsh[(2 * 4 + g) * 64 + d] + wsh[(3 * 4 + g) * 64 + d];
        out[(size_t)(i0 + g) * 64 + d] = r * inv[g];
    }
}

// ---------------------------------------------------------------------------
extern "C" void kernel_launch(void* const* d_in, const int* in_sizes, int n_in,
                              void* d_out, int out_size)
{
    (void)out_size;
    const float *H = nullptr, *Dm = nullptr, *Wp = nullptr;
    for (int i = 0; i < n_in; i++) {
        if      (in_sizes[i] == NN * DIN)  H  = (const float*)d_in[i];
        else if (in_sizes[i] == DIN * DIN) Wp = (const float*)d_in[i];
        else                               Dm = (const float*)d_in[i];
    }

    float* proj = nullptr;
    float* Sp   = nullptr;
    cudaGetSymbolAddress((void**)&proj, g_proj);
    cudaGetSymbolAddress((void**)&Sp,   g_S);

    const float scale = 0.08838834764831845f;   // 1/sqrt(128)

    // 1) proj = H @ W^T   (2048 x 256)
    gemm_nt<<<dim3(DIN / 64, NN / 64), 256>>>(H, DIN, Wp, DIN, proj, DIN, DIN, 1.0f);
    // 2) S = scale * Q @ K^T   (2048 x 2048)
    gemm_nt<<<dim3(NN / 64, NN / 64), 256>>>(proj, DIN, proj + 64, DIN, Sp, NN, 64, scale);
    // 3) fused RD + softmax + @V
    attn_main<<<NN / 4, 256>>>(Dm, proj, Sp, (float*)d_out);
}